// round 14
// baseline (speedup 1.0000x reference)
#include <cuda_runtime.h>
#include <cstdint>

#define BATCH 4
#define DS 16
#define NO 2048
#define NR 16384
#define DR 8
#define DE 64
#define DX 8
#define DP 64
#define NC 10

#define NF 40               // Bm feature rows (2*DS + DR)
#define NFP 48              // padded to 6 n-tiles (row 40 = ones -> s, 41..47 zero)

// kernelA tiling (HMMA GEMM over o)
#define RT 256              // r per CTA
#define KCA 16              // o per chunk
#define NCHA (NO / KCA)     // 128 chunks
#define PITA 528            // stage tile o-row pitch bytes
#define OPIT 48             // O tile d-row pitch bytes

// kernelB tiling: CTA 64o x 48f, 128 threads, 4 CTAs/SM
#define ZB 4
#define KZ (NR / ZB)        // 4096 r per z-split
#define KC 32               // r per chunk
#define NCH (KZ / KC)       // 128 chunks
#define PITCH 80            // smem row pitch bytes
// per-buffer: Ah(64*80) | Al | Bh(48*80) | Bl
#define BOF_AL 5120
#define BOF_BH 10240
#define BOF_BL 14080
#define BUFSZ  17920

typedef unsigned long long u64;
typedef unsigned short u16;

// Scratch (allocation-free rule: __device__ globals)
__device__ u16  g_Mhi[(size_t)BATCH * NF * NR];        // 5.2 MB  Bm hi limb
__device__ u16  g_Mlo[(size_t)BATCH * NF * NR];        // 5.2 MB  Bm lo limb
__device__ float g_Ehp[(size_t)ZB * BATCH * NO * NFP]; // 6.3 MB  G partials [z][b][o][48]

// ---- packed fp32x2 helpers (FFMA2) ----
__device__ __forceinline__ u64 ffma2(u64 a, u64 b, u64 c) {
    u64 d;
    asm("fma.rn.f32x2 %0, %1, %2, %3;" : "=l"(d) : "l"(a), "l"(b), "l"(c));
    return d;
}
__device__ __forceinline__ u64 pack2(float lo, float hi) {
    u64 r;
    asm("mov.b64 %0, {%1, %2};" : "=l"(r) : "f"(lo), "f"(hi));
    return r;
}
__device__ __forceinline__ float2 unpack2(u64 v) {
    float2 f;
    asm("mov.b64 {%0, %1}, %2;" : "=f"(f.x), "=f"(f.y) : "l"(v));
    return f;
}
__device__ __forceinline__ uint32_t smem_u32(const void* p) {
    uint32_t a;
    asm("{ .reg .u64 t; cvta.to.shared.u64 t, %1; cvt.u32.u64 %0, t; }" : "=r"(a) : "l"(p));
    return a;
}
// split (x0,x1) -> packed bf16x2 hi limb + packed bf16x2 lo residual (x0 in LOW half)
__device__ __forceinline__ void split2(float x0, float x1, uint32_t& hi, uint32_t& lo) {
    asm("cvt.rn.bf16x2.f32 %0, %1, %2;" : "=r"(hi) : "f"(x1), "f"(x0));
    float h0 = __uint_as_float(hi << 16);
    float h1 = __uint_as_float(hi & 0xFFFF0000u);
    float r0 = x0 - h0, r1 = x1 - h1;
    asm("cvt.rn.bf16x2.f32 %0, %1, %2;" : "=r"(lo) : "f"(r1), "f"(r0));
}
__device__ __forceinline__ void sts64(uint32_t a, uint32_t x, uint32_t y) {
    asm volatile("st.shared.v2.b32 [%0], {%1,%2};" :: "r"(a), "r"(x), "r"(y) : "memory");
}
__device__ __forceinline__ void sts128(uint32_t a, uint32_t x, uint32_t y, uint32_t z, uint32_t w) {
    asm volatile("st.shared.v4.b32 [%0], {%1,%2,%3,%4};" :: "r"(a), "r"(x), "r"(y), "r"(z), "r"(w) : "memory");
}
__device__ __forceinline__ void ldm_x4(uint32_t* r, uint32_t addr) {
    asm volatile("ldmatrix.sync.aligned.m8n8.x4.shared.b16 {%0,%1,%2,%3}, [%4];"
                 : "=r"(r[0]), "=r"(r[1]), "=r"(r[2]), "=r"(r[3]) : "r"(addr));
}
__device__ __forceinline__ void ldm_x4t(uint32_t* r, uint32_t addr) {
    asm volatile("ldmatrix.sync.aligned.m8n8.x4.trans.shared.b16 {%0,%1,%2,%3}, [%4];"
                 : "=r"(r[0]), "=r"(r[1]), "=r"(r[2]), "=r"(r[3]) : "r"(addr));
}
__device__ __forceinline__ void mma16816(float* d, const uint32_t* a, const uint32_t* b) {
    asm volatile(
        "mma.sync.aligned.m16n8k16.row.col.f32.bf16.bf16.f32 "
        "{%0,%1,%2,%3}, {%4,%5,%6,%7}, {%8,%9}, {%0,%1,%2,%3};"
        : "+f"(d[0]), "+f"(d[1]), "+f"(d[2]), "+f"(d[3])
        : "r"(a[0]), "r"(a[1]), "r"(a[2]), "r"(a[3]), "r"(b[0]), "r"(b[1]));
}

// ============================================================================
// Kernel A: M1/M2 via HMMA; writes Bm = [M1;M2;Ra] as bf16 hi/lo limbs.
// grid (NR/256, BATCH) = 256 CTAs. (R12: 164us, 83% DRAM — unchanged)
// ============================================================================
__global__ void __launch_bounds__(256, 2)
kernelA(const float* __restrict__ O, const float* __restrict__ Rs,
        const float* __restrict__ Rr, const float* __restrict__ Ra)
{
    __shared__ __align__(16) char sStage[34816];
    __shared__ __align__(16) char sOt[2 * DS * OPIT];

    const int tid = threadIdx.x;
    const int wid = tid >> 5;
    const int lid = tid & 31;
    const int b   = blockIdx.y;
    const int r0  = blockIdx.x * RT;

    const uint32_t uSt  = smem_u32(sStage);
    const uint32_t uRsH = uSt, uRsL = uSt + 8448, uRrH = uSt + 16896, uRrL = uSt + 25344;
    const uint32_t uOH  = smem_u32(sOt);

    const float* Rsb = Rs + (size_t)b * NO * NR + r0;
    const float* Rrb = Rr + (size_t)b * NO * NR + r0;
    const float* Ob  = O  + (size_t)b * DS * NO;

    float accS[2][2][4], accR[2][2][4];
#pragma unroll
    for (int i = 0; i < 2; i++)
#pragma unroll
        for (int j = 0; j < 2; j++)
#pragma unroll
            for (int v = 0; v < 4; v++) { accS[i][j][v] = 0.f; accR[i][j][v] = 0.f; }

    const int so = tid >> 6;
    const int c4 = tid & 63;
    const int od = tid >> 4;
    const int oo = tid & 15;

    const uint32_t krow = (uint32_t)((lid & 7) + ((lid >> 4) << 3));
    const uint32_t mcol = (uint32_t)(((lid >> 3) & 1) << 3);
    const uint32_t brow_ = (uint32_t)(((lid >> 4) << 3) + (lid & 7));
    const uint32_t bcol_ = (uint32_t)(((lid >> 3) & 1) << 3);

    float4 pS[4], pR[4];
    float  pO;

#define LOADA(cb) do {                                                        \
    _Pragma("unroll")                                                         \
    for (int q = 0; q < 4; q++) {                                             \
        size_t row = (size_t)((cb) + q * 4 + so) * NR;                        \
        pS[q] = *(const float4*)(Rsb + row + c4 * 4);                         \
        pR[q] = *(const float4*)(Rrb + row + c4 * 4);                         \
    }                                                                         \
    pO = Ob[(size_t)od * NO + (cb) + oo];                                     \
} while (0)

    LOADA(0);

    for (int kc = 0; kc < NCHA; kc++) {
        __syncthreads();

#pragma unroll
        for (int q = 0; q < 4; q++) {
            uint32_t h0, l0, h1, l1;
            uint32_t off = (uint32_t)(q * 4 + so) * PITA + (uint32_t)c4 * 8;
            split2(pS[q].x, pS[q].y, h0, l0);
            split2(pS[q].z, pS[q].w, h1, l1);
            sts64(uRsH + off, h0, h1);
            sts64(uRsL + off, l0, l1);
            split2(pR[q].x, pR[q].y, h0, l0);
            split2(pR[q].z, pR[q].w, h1, l1);
            sts64(uRrH + off, h0, h1);
            sts64(uRrL + off, l0, l1);
        }
        {
            uint32_t h32, l32;
            split2(pO, 0.f, h32, l32);
            *(u16*)(sOt + od * OPIT + oo * 2)             = (u16)h32;
            *(u16*)(sOt + DS * OPIT + od * OPIT + oo * 2) = (u16)l32;
        }
        __syncthreads();

        if (kc + 1 < NCHA) LOADA((kc + 1) * KCA);

        uint32_t bOh[4], bOl[4];
        {
            uint32_t oaddr = uOH + brow_ * OPIT + bcol_ * 2;
            ldm_x4(bOh, oaddr);
            ldm_x4(bOl, oaddr + DS * OPIT);
        }
#pragma unroll
        for (int mt = 0; mt < 2; mt++) {
            uint32_t aoff = krow * PITA + (uint32_t)(wid * 32 + mt * 16) * 2 + mcol * 2;
            uint32_t ash[4], asl[4], arh[4], arl[4];
            ldm_x4t(ash, uRsH + aoff);
            ldm_x4t(asl, uRsL + aoff);
            ldm_x4t(arh, uRrH + aoff);
            ldm_x4t(arl, uRrL + aoff);
#pragma unroll
            for (int nt = 0; nt < 2; nt++) {
                mma16816(accS[mt][nt], ash, bOh + nt * 2);
                mma16816(accS[mt][nt], ash, bOl + nt * 2);
                mma16816(accS[mt][nt], asl, bOh + nt * 2);
                mma16816(accR[mt][nt], arh, bOh + nt * 2);
                mma16816(accR[mt][nt], arh, bOl + nt * 2);
                mma16816(accR[mt][nt], arl, bOh + nt * 2);
            }
        }
    }
#undef LOADA

    __syncthreads();
    float* sM = (float*)sStage;
#pragma unroll
    for (int mt = 0; mt < 2; mt++) {
        int rl = wid * 32 + mt * 16 + (lid >> 2);
#pragma unroll
        for (int nt = 0; nt < 2; nt++) {
            int c = nt * 8 + (lid & 3) * 2;
            *(float2*)(sM + rl * 34 + c)            = make_float2(accS[mt][nt][0], accS[mt][nt][1]);
            *(float2*)(sM + (rl + 8) * 34 + c)      = make_float2(accS[mt][nt][2], accS[mt][nt][3]);
            *(float2*)(sM + rl * 34 + 16 + c)       = make_float2(accR[mt][nt][0], accR[mt][nt][1]);
            *(float2*)(sM + (rl + 8) * 34 + 16 + c) = make_float2(accR[mt][nt][2], accR[mt][nt][3]);
        }
    }
    __syncthreads();

    const int r = tid;
    const float* mrow = sM + r * 34;
    u16* MH = g_Mhi + (size_t)b * NF * NR + r0 + r;
    u16* ML = g_Mlo + (size_t)b * NF * NR + r0 + r;
#pragma unroll 8
    for (int f = 0; f < 32; f++) {
        uint32_t h32, l32;
        split2(mrow[f], 0.f, h32, l32);
        MH[(size_t)f * NR] = (u16)h32;
        ML[(size_t)f * NR] = (u16)l32;
    }
    const float* Rab = Ra + (size_t)b * DR * NR + r0 + r;
#pragma unroll
    for (int j = 0; j < 8; j++) {
        uint32_t h32, l32;
        split2(Rab[(size_t)j * NR], 0.f, h32, l32);
        MH[(size_t)(32 + j) * NR] = (u16)h32;
        ML[(size_t)(32 + j) * NR] = (u16)l32;
    }
}

// ============================================================================
// Kernel B: G[z][b][o][f] = sum_{r in z} Rr[b,o,r] * Bm[b,f,r]  (f<40),
// f=40 -> s[o]. bf16 3-limb mma. CTA 64o x 48f, block 128 (4 warps),
// 4 CTAs/SM for cross-CTA phase overlap. R12 pipeline structure
// (double-buffered smem, distance-1 reg prefetch).
// grid (32, BATCH, ZB=4) = 512 CTAs.
// ============================================================================
__global__ void __launch_bounds__(128, 4)
kernelB(const float* __restrict__ Rr)
{
    extern __shared__ __align__(128) char sB[];

    const int tid = threadIdx.x;
    const int wid = tid >> 5;
    const int lid = tid & 31;
    const int o0  = blockIdx.x * 64;
    const int b   = blockIdx.y;
    const int z   = blockIdx.z;

    const uint32_t uB0 = smem_u32(sB);

    const float* Ag  = Rr    + (size_t)b * NO * NR + (size_t)z * KZ;
    const u16*   BgH = g_Mhi + (size_t)b * NF * NR + (size_t)z * KZ;
    const u16*   BgL = g_Mlo + (size_t)b * NF * NR + (size_t)z * KZ;

    // staging maps (128 threads):
    // A tile 64 rows x 32 floats: arow = tid>>1 (0..63), akh = (tid&1)*16
    // B tiles 40 rows x 32 u16 per limb: brow = tid>>1 (0..63), bq = (tid&1)*16
    const int arow = tid >> 1, akh = (tid & 1) * 16;
    const int brow = tid >> 1, bq  = (tid & 1) * 16;

    const uint32_t a_lrow = (uint32_t)((wid * 16) + (((lid >> 3) & 1) * 8) + (lid & 7));
    const uint32_t a_lcol = (uint32_t)((lid >> 4) * 8);
    const uint32_t b_lrow = (uint32_t)((((lid >> 3) >> 1) * 8) + (lid & 7));
    const uint32_t b_lcol = (uint32_t)(((lid >> 3) & 1) * 8);

    // init constant rows 40..47 of B tiles (both buffers, both limbs):
    // row 40 hi = bf16 ones (-> s), everything else zero.
    for (int idx = tid; idx < 640; idx += 128) {
        int region = idx / 160;                 // 0:b0Bh 1:b0Bl 2:b1Bh 3:b1Bl
        int off = (idx - region * 160) * 4;
        int byteoff = (region >> 1) * BUFSZ + ((region & 1) ? BOF_BL : BOF_BH)
                    + 40 * PITCH + off;
        uint32_t val = (((region & 1) == 0) && off < PITCH) ? 0x3F803F80u : 0u;
        *(uint32_t*)(sB + byteoff) = val;
    }

    float acc[6][4];
#pragma unroll
    for (int j = 0; j < 6; j++)
#pragma unroll
        for (int v = 0; v < 4; v++) acc[j][v] = 0.f;

    float4 av[4];
    uint4  bvh[2], bvl[2];

#define LOADB(cb) do {                                                        \
    const float* ap = Ag + (size_t)(o0 + arow) * NR + (cb) + akh;             \
    _Pragma("unroll")                                                         \
    for (int q = 0; q < 4; q++) av[q] = *(const float4*)(ap + 4 * q);         \
    if (brow < NF) {                                                          \
        const u16* sh = BgH + (size_t)brow * NR + (cb) + bq;                  \
        const u16* sl = BgL + (size_t)brow * NR + (cb) + bq;                  \
        bvh[0] = *(const uint4*)sh;  bvh[1] = *(const uint4*)(sh + 8);        \
        bvl[0] = *(const uint4*)sl;  bvl[1] = *(const uint4*)(sl + 8);        \
    }                                                                         \
} while (0)

#define STOREB(base) do {                                                     \
    _Pragma("unroll")                                                         \
    for (int q = 0; q < 4; q++) {                                             \
        uint32_t h0, h1, l0, l1;                                              \
        split2(av[q].x, av[q].y, h0, l0);                                     \
        split2(av[q].z, av[q].w, h1, l1);                                     \
        uint32_t off = (uint32_t)arow * PITCH + (uint32_t)(akh + 4 * q) * 2;  \
        sts64((base) + off, h0, h1);                                          \
        sts64((base) + BOF_AL + off, l0, l1);                                 \
    }                                                                         \
    if (brow < NF) {                                                          \
        uint32_t off = (uint32_t)brow * PITCH + (uint32_t)bq * 2;             \
        sts128((base) + BOF_BH + off,      bvh[0].x, bvh[0].y, bvh[0].z, bvh[0].w); \
        sts128((base) + BOF_BH + off + 16, bvh[1].x, bvh[1].y, bvh[1].z, bvh[1].w); \
        sts128((base) + BOF_BL + off,      bvl[0].x, bvl[0].y, bvl[0].z, bvl[0].w); \
        sts128((base) + BOF_BL + off + 16, bvl[1].x, bvl[1].y, bvl[1].z, bvl[1].w); \
    }                                                                         \
} while (0)

    // prologue: chunk 0 -> buf 0
    LOADB(0);
    STOREB(uB0);
    __syncthreads();

    for (int kc = 0; kc < NCH; kc++) {
        const uint32_t cbase = uB0 + (uint32_t)(kc & 1) * BUFSZ;
        const uint32_t nbase = uB0 + (uint32_t)((kc + 1) & 1) * BUFSZ;

        if (kc + 1 < NCH) LOADB((kc + 1) * KC);

        // compute chunk kc
#pragma unroll
        for (int ks = 0; ks < 2; ks++) {
            const uint32_t koff = (uint32_t)(ks * 16) * 2;
            uint32_t ah[4], al[4];
            uint32_t bh[6][2], bl[6][2];
            {
                uint32_t addr = cbase + a_lrow * PITCH + a_lcol * 2 + koff;
                ldm_x4(ah, addr);
                ldm_x4(al, addr + BOF_AL);
            }
#pragma unroll
            for (int tp = 0; tp < 3; tp++) {
                uint32_t addr = cbase + BOF_BH + (b_lrow + tp * 16) * PITCH + b_lcol * 2 + koff;
                uint32_t rh[4], rl[4];
                ldm_x4(rh, addr);
                ldm_x4(rl, addr + (BOF_BL - BOF_BH));
                bh[2 * tp][0] = rh[0]; bh[2 * tp][1] = rh[1];
                bh[2 * tp + 1][0] = rh[2]; bh[2 * tp + 1][1] = rh[3];
                bl[2 * tp][0] = rl[0]; bl[2 * tp][1] = rl[1];
                bl[2 * tp + 1][0] = rl[2]; bl[2 * tp + 1][1] = rl[3];
            }
#pragma unroll
            for (int nt = 0; nt < 5; nt++) {
                mma16816(acc[nt], ah, bh[nt]);
                mma16816(acc[nt], ah, bl[nt]);
                mma16816(acc[nt], al, bh[nt]);
            }
            mma16816(acc[5], ah, bh[5]);
            mma16816(acc[5], al, bh[5]);
        }

        if (kc + 1 < NCH) STOREB(nbase);
        __syncthreads();
    }
#undef LOADB
#undef STOREB

    // epilogue: D frag -> g_Ehp[z][b][o][48]
    float* outb = g_Ehp + ((size_t)(z * BATCH + b) * NO) * NFP;
    int o = o0 + wid * 16 + (lid >> 2);
#pragma unroll
    for (int nt = 0; nt < 6; nt++) {
        int f = nt * 8 + (lid & 3) * 2;
        *(float2*)(outb + (size_t)o * NFP + f)       = make_float2(acc[nt][0], acc[nt][1]);
        *(float2*)(outb + (size_t)(o + 8) * NFP + f) = make_float2(acc[nt][2], acc[nt][3]);
    }
}

// ============================================================================
// Kernel C: fold W_r into the object model:
//   P = W_ox@[O;X] + Wc@G + wb*s + b_o ; scores = W_s@P + b_s ; softmax.
// ============================================================================
__global__ void __launch_bounds__(128, 1)
kernelC(const float* __restrict__ O, const float* __restrict__ X,
        const float* __restrict__ Wr, const float* __restrict__ br,
        const float* __restrict__ Wo, const float* __restrict__ bo,
        const float* __restrict__ Ws, const float* __restrict__ bs,
        float* __restrict__ out)
{
    __shared__ u64 sWox[24 * 32];
    __shared__ u64 sWc[NF * 32];
    __shared__ u64 sWoE[64 * 32];
    __shared__ float sWr[64 * NF];
    __shared__ u64 sWs[NC * 32];
    __shared__ u64 swb[32];
    __shared__ float sbo[DP];
    __shared__ float sbs[NC];
    __shared__ float sbr_[DE];

    const int tid = threadIdx.x;
    const int b   = blockIdx.y;
    const int o   = blockIdx.x * 128 + tid;

    for (int idx = tid; idx < 24 * 32; idx += 128) {
        int f = idx >> 5, p2 = idx & 31;
        sWox[idx] = pack2(Wo[(size_t)(2 * p2) * 88 + f],
                          Wo[(size_t)(2 * p2 + 1) * 88 + f]);
    }
    for (int idx = tid; idx < 64 * 32; idx += 128) {
        int e = idx >> 5, p2 = idx & 31;
        sWoE[idx] = pack2(Wo[(size_t)(2 * p2) * 88 + 24 + e],
                          Wo[(size_t)(2 * p2 + 1) * 88 + 24 + e]);
    }
    for (int idx = tid; idx < 64 * NF; idx += 128) sWr[idx] = Wr[idx];
    for (int idx = tid; idx < NC * 32; idx += 128) {
        int c = idx >> 5, p2 = idx & 31;
        float2 w = *(const float2*)(Ws + (size_t)c * DP + 2 * p2);
        sWs[idx] = pack2(w.x, w.y);
    }
    if (tid < DP) sbo[tid] = bo[tid];
    if (tid < NC) sbs[tid] = bs[tid];
    if (tid < DE) sbr_[tid] = br[tid];
    __syncthreads();

    for (int idx = tid; idx < NF * 32; idx += 128) {
        int f = idx >> 5, p2 = idx & 31;
        u64 a = 0ull;
#pragma unroll 8
        for (int e = 0; e < 64; e++) {
            float w = sWr[e * NF + f];
            a = ffma2(sWoE[e * 32 + p2], pack2(w, w), a);
        }
        sWc[idx] = a;
    }
    if (tid < 32) {
        u64 a = 0ull;
#pragma unroll 8
        for (int e = 0; e < 64; e++)
            a = ffma2(sWoE[e * 32 + tid], pack2(sbr_[e], sbr_[e]), a);
        swb[tid] = a;
    }
    __syncthreads();

    u64 P[32];
#pragma unroll
    for (int p2 = 0; p2 < 32; p2++) P[p2] = pack2(sbo[2 * p2], sbo[2 * p2 + 1]);

    const float* Ob = O + (size_t)b * DS * NO + o;
    const float* Xb = X + (size_t)b * DX * NO + o;

#pragma unroll 4
    for (int f = 0; f < DS; f++) {
        float cf = Ob[(size_t)f * NO];
        u64 c2 = pack2(cf, cf);
        const u64* wrow = sWox + f * 32;
#pragma unroll
        for (int p2 = 0; p2 < 32; p2++) P[p2] = ffma2(wrow[p2], c2, P[p2]);
    }
#pragma unroll 4
    for (int f = 0; f < DX; f++) {
        float cf = Xb[(size_t)f * NO];
        u64 c2 = pack2(cf, cf);
        const u64* wrow = sWox + (DS + f) * 32;
#pragma unroll
        for (int p2 = 0; p2 < 32; p2++) P[p2] = ffma2(wrow[p2], c2, P[p2]);
    }

    const float* ep0 = g_Ehp + ((size_t)b * NO + o) * NFP;
    const size_t SSTR = (size_t)BATCH * NO * NFP;
#pragma unroll 2
    for (int f4 = 0; f4 < 10; f4++) {
        float4 v0 = *(const float4*)(ep0 + 4 * f4);
        float4 v1 = *(const float4*)(ep0 + SSTR + 4 * f4);
        float4 v2 = *(const float4*)(ep0 + 2 * SSTR + 4 * f4);
        float4 v3 = *(const float4*)(ep0 + 3 * SSTR + 4 * f4);
        float cf[4] = {(v0.x + v1.x) + (v2.x + v3.x),
                       (v0.y + v1.y) + (v2.y + v3.y),
                       (v0.z + v1.z) + (v2.z + v3.z),
                       (v0.w + v1.w) + (v2.w + v3.w)};
#pragma unroll
        for (int j = 0; j < 4; j++) {
            u64 c2 = pack2(cf[j], cf[j]);
            const u64* wrow = sWc + (4 * f4 + j) * 32;
#pragma unroll
            for (int p2 = 0; p2 < 32; p2++) P[p2] = ffma2(wrow[p2], c2, P[p2]);
        }
    }
    {
        float s = (ep0[40] + ep0[40 + SSTR]) + (ep0[40 + 2 * SSTR] + ep0[40 + 3 * SSTR]);
        u64 c2 = pack2(s, s);
#pragma unroll
        for (int p2 = 0; p2 < 32; p2++) P[p2] = ffma2(swb[p2], c2, P[p2]);
    }

    float sc[NC];
#pragma unroll
    for (int c = 0; c < NC; c++) {
        const u64* wrow = sWs + c * 32;
        u64 acc = 0ull;
#pragma unroll
        for (int p2 = 0; p2 < 32; p2++) acc = ffma2(wrow[p2], P[p2], acc);
        float2 a = unpack2(acc);
        sc[c] = a.x + a.y + sbs[c];
    }

    float mx = sc[0];
#pragma unroll
    for (int c = 1; c < NC; c++) mx = fmaxf(mx, sc[c]);
    float sum = 0.f;
#pragma unroll
    for (int c = 0; c < NC; c++) { sc[c] = expf(sc[c] - mx); sum += sc[c]; }
    float inv = 1.f / sum;
#pragma unroll
    for (int c = 0; c < NC; c++)
        out[((size_t)b * NC + c) * NO + o] = sc[c] * inv;
}

// ============================================================================
extern "C" void kernel_launch(void* const* d_in, const int* in_sizes, int n_in,
                              void* d_out, int out_size)
{
    const float* O  = (const float*)d_in[0];
    const float* Rs = (const float*)d_in[1];
    const float* Rr = (const float*)d_in[2];
    const float* Ra = (const float*)d_in[3];
    const float* X  = (const float*)d_in[4];
    const float* Wr = (const float*)d_in[5];
    const float* br = (const float*)d_in[6];
    const float* Wo = (const float*)d_in[7];
    const float* bo = (const float*)d_in[8];
    const float* Ws = (const float*)d_in[9];
    const float* bs = (const float*)d_in[10];
    float* out = (float*)d_out;
    (void)in_sizes; (void)n_in; (void)out_size;

    int smB = 2 * BUFSZ;   // 35840 B
    cudaFuncSetAttribute(kernelB, cudaFuncAttributeMaxDynamicSharedMemorySize, smB);

    kernelA<<<dim3(NR / RT, BATCH), 256>>>(O, Rs, Rr, Ra);
    kernelB<<<dim3(NO / 64, BATCH, ZB), 128, smB>>>(Rr);
    kernelC<<<dim3(NO / 128, BATCH), 128>>>(O, X, Wr, br, Wo, bo, Ws, bs, out);
}

// round 15
// speedup vs baseline: 1.1904x; 1.1904x over previous
#include <cuda_runtime.h>
#include <cstdint>

#define BATCH 4
#define DS 16
#define NO 2048
#define NR 16384
#define DR 8
#define DE 64
#define DX 8
#define DP 64
#define NC 10

#define NF 40               // Bm feature rows (2*DS + DR)
#define NFP 48              // padded to 6 n-tiles (row 40 = ones -> s, 41..47 zero)

// kernelA tiling (HMMA GEMM over o)
#define RT 256              // r per CTA
#define KCA 16              // o per chunk
#define NCHA (NO / KCA)     // 128 chunks
#define PITA 528            // stage tile o-row pitch bytes
#define OPIT 48             // O tile d-row pitch bytes

// kernelB tiling: CTA 128o x 48f, 256 threads, 4-stage cp.async pipeline
#define ZB 4
#define KZ (NR / ZB)        // 4096 r per z-split
#define KC 32               // r per chunk
#define NCH (KZ / KC)       // 128 chunks
#define NST 4               // pipeline stages
#define APIT 160            // A (fp32) row pitch bytes: conflict-free, 16B-mult
#define BPIT 80             // B (bf16 limb) row pitch bytes
// per-stage: Afp32 (128*160) | Bh (48*80) | Bl (48*80)
#define SOF_BH 20480
#define SOF_BL 24320
#define STSZ   28160

typedef unsigned long long u64;
typedef unsigned short u16;

// Scratch (allocation-free rule: __device__ globals)
__device__ u16  g_Mhi[(size_t)BATCH * NF * NR];        // 5.2 MB  Bm hi limb
__device__ u16  g_Mlo[(size_t)BATCH * NF * NR];        // 5.2 MB  Bm lo limb
__device__ float g_Ehp[(size_t)ZB * BATCH * NO * NFP]; // 6.3 MB  G partials [z][b][o][48]

// ---- packed fp32x2 helpers (FFMA2) ----
__device__ __forceinline__ u64 ffma2(u64 a, u64 b, u64 c) {
    u64 d;
    asm("fma.rn.f32x2 %0, %1, %2, %3;" : "=l"(d) : "l"(a), "l"(b), "l"(c));
    return d;
}
__device__ __forceinline__ u64 pack2(float lo, float hi) {
    u64 r;
    asm("mov.b64 %0, {%1, %2};" : "=l"(r) : "f"(lo), "f"(hi));
    return r;
}
__device__ __forceinline__ float2 unpack2(u64 v) {
    float2 f;
    asm("mov.b64 {%0, %1}, %2;" : "=f"(f.x), "=f"(f.y) : "l"(v));
    return f;
}
__device__ __forceinline__ uint32_t smem_u32(const void* p) {
    uint32_t a;
    asm("{ .reg .u64 t; cvta.to.shared.u64 t, %1; cvt.u32.u64 %0, t; }" : "=r"(a) : "l"(p));
    return a;
}
// split (x0,x1) -> packed bf16x2 hi limb + packed bf16x2 lo residual (x0 in LOW half)
__device__ __forceinline__ void split2(float x0, float x1, uint32_t& hi, uint32_t& lo) {
    asm("cvt.rn.bf16x2.f32 %0, %1, %2;" : "=r"(hi) : "f"(x1), "f"(x0));
    float h0 = __uint_as_float(hi << 16);
    float h1 = __uint_as_float(hi & 0xFFFF0000u);
    float r0 = x0 - h0, r1 = x1 - h1;
    asm("cvt.rn.bf16x2.f32 %0, %1, %2;" : "=r"(lo) : "f"(r1), "f"(r0));
}
__device__ __forceinline__ void sts64(uint32_t a, uint32_t x, uint32_t y) {
    asm volatile("st.shared.v2.b32 [%0], {%1,%2};" :: "r"(a), "r"(x), "r"(y) : "memory");
}
__device__ __forceinline__ float2 lds64f(uint32_t a) {
    float2 v;
    asm volatile("ld.shared.v2.f32 {%0,%1}, [%2];" : "=f"(v.x), "=f"(v.y) : "r"(a));
    return v;
}
__device__ __forceinline__ void ldm_x4(uint32_t* r, uint32_t addr) {
    asm volatile("ldmatrix.sync.aligned.m8n8.x4.shared.b16 {%0,%1,%2,%3}, [%4];"
                 : "=r"(r[0]), "=r"(r[1]), "=r"(r[2]), "=r"(r[3]) : "r"(addr));
}
__device__ __forceinline__ void ldm_x4t(uint32_t* r, uint32_t addr) {
    asm volatile("ldmatrix.sync.aligned.m8n8.x4.trans.shared.b16 {%0,%1,%2,%3}, [%4];"
                 : "=r"(r[0]), "=r"(r[1]), "=r"(r[2]), "=r"(r[3]) : "r"(addr));
}
__device__ __forceinline__ void mma16816(float* d, const uint32_t* a, const uint32_t* b) {
    asm volatile(
        "mma.sync.aligned.m16n8k16.row.col.f32.bf16.bf16.f32 "
        "{%0,%1,%2,%3}, {%4,%5,%6,%7}, {%8,%9}, {%0,%1,%2,%3};"
        : "+f"(d[0]), "+f"(d[1]), "+f"(d[2]), "+f"(d[3])
        : "r"(a[0]), "r"(a[1]), "r"(a[2]), "r"(a[3]), "r"(b[0]), "r"(b[1]));
}
__device__ __forceinline__ void cpasync16(uint32_t dst, const void* src) {
    asm volatile("{ .reg .u64 g; cvta.to.global.u64 g, %1;\n\t"
                 "cp.async.cg.shared.global [%0], [g], 16; }"
                 :: "r"(dst), "l"(src) : "memory");
}
#define CP_COMMIT() asm volatile("cp.async.commit_group;" ::: "memory")
#define CP_WAIT2()  asm volatile("cp.async.wait_group 2;" ::: "memory")

// ============================================================================
// Kernel A: M1/M2 via HMMA; writes Bm = [M1;M2;Ra] as bf16 hi/lo limbs.
// grid (NR/256, BATCH) = 256 CTAs. (R12: 164us, 83% DRAM — unchanged)
// ============================================================================
__global__ void __launch_bounds__(256, 2)
kernelA(const float* __restrict__ O, const float* __restrict__ Rs,
        const float* __restrict__ Rr, const float* __restrict__ Ra)
{
    __shared__ __align__(16) char sStage[34816];
    __shared__ __align__(16) char sOt[2 * DS * OPIT];

    const int tid = threadIdx.x;
    const int wid = tid >> 5;
    const int lid = tid & 31;
    const int b   = blockIdx.y;
    const int r0  = blockIdx.x * RT;

    const uint32_t uSt  = smem_u32(sStage);
    const uint32_t uRsH = uSt, uRsL = uSt + 8448, uRrH = uSt + 16896, uRrL = uSt + 25344;
    const uint32_t uOH  = smem_u32(sOt);

    const float* Rsb = Rs + (size_t)b * NO * NR + r0;
    const float* Rrb = Rr + (size_t)b * NO * NR + r0;
    const float* Ob  = O  + (size_t)b * DS * NO;

    float accS[2][2][4], accR[2][2][4];
#pragma unroll
    for (int i = 0; i < 2; i++)
#pragma unroll
        for (int j = 0; j < 2; j++)
#pragma unroll
            for (int v = 0; v < 4; v++) { accS[i][j][v] = 0.f; accR[i][j][v] = 0.f; }

    const int so = tid >> 6;
    const int c4 = tid & 63;
    const int od = tid >> 4;
    const int oo = tid & 15;

    const uint32_t krow = (uint32_t)((lid & 7) + ((lid >> 4) << 3));
    const uint32_t mcol = (uint32_t)(((lid >> 3) & 1) << 3);
    const uint32_t brow_ = (uint32_t)(((lid >> 4) << 3) + (lid & 7));
    const uint32_t bcol_ = (uint32_t)(((lid >> 3) & 1) << 3);

    float4 pS[4], pR[4];
    float  pO;

#define LOADA(cb) do {                                                        \
    _Pragma("unroll")                                                         \
    for (int q = 0; q < 4; q++) {                                             \
        size_t row = (size_t)((cb) + q * 4 + so) * NR;                        \
        pS[q] = *(const float4*)(Rsb + row + c4 * 4);                         \
        pR[q] = *(const float4*)(Rrb + row + c4 * 4);                         \
    }                                                                         \
    pO = Ob[(size_t)od * NO + (cb) + oo];                                     \
} while (0)

    LOADA(0);

    for (int kc = 0; kc < NCHA; kc++) {
        __syncthreads();

#pragma unroll
        for (int q = 0; q < 4; q++) {
            uint32_t h0, l0, h1, l1;
            uint32_t off = (uint32_t)(q * 4 + so) * PITA + (uint32_t)c4 * 8;
            split2(pS[q].x, pS[q].y, h0, l0);
            split2(pS[q].z, pS[q].w, h1, l1);
            sts64(uRsH + off, h0, h1);
            sts64(uRsL + off, l0, l1);
            split2(pR[q].x, pR[q].y, h0, l0);
            split2(pR[q].z, pR[q].w, h1, l1);
            sts64(uRrH + off, h0, h1);
            sts64(uRrL + off, l0, l1);
        }
        {
            uint32_t h32, l32;
            split2(pO, 0.f, h32, l32);
            *(u16*)(sOt + od * OPIT + oo * 2)             = (u16)h32;
            *(u16*)(sOt + DS * OPIT + od * OPIT + oo * 2) = (u16)l32;
        }
        __syncthreads();

        if (kc + 1 < NCHA) LOADA((kc + 1) * KCA);

        uint32_t bOh[4], bOl[4];
        {
            uint32_t oaddr = uOH + brow_ * OPIT + bcol_ * 2;
            ldm_x4(bOh, oaddr);
            ldm_x4(bOl, oaddr + DS * OPIT);
        }
#pragma unroll
        for (int mt = 0; mt < 2; mt++) {
            uint32_t aoff = krow * PITA + (uint32_t)(wid * 32 + mt * 16) * 2 + mcol * 2;
            uint32_t ash[4], asl[4], arh[4], arl[4];
            ldm_x4t(ash, uRsH + aoff);
            ldm_x4t(asl, uRsL + aoff);
            ldm_x4t(arh, uRrH + aoff);
            ldm_x4t(arl, uRrL + aoff);
#pragma unroll
            for (int nt = 0; nt < 2; nt++) {
                mma16816(accS[mt][nt], ash, bOh + nt * 2);
                mma16816(accS[mt][nt], ash, bOl + nt * 2);
                mma16816(accS[mt][nt], asl, bOh + nt * 2);
                mma16816(accR[mt][nt], arh, bOh + nt * 2);
                mma16816(accR[mt][nt], arh, bOl + nt * 2);
                mma16816(accR[mt][nt], arl, bOh + nt * 2);
            }
        }
    }
#undef LOADA

    __syncthreads();
    float* sM = (float*)sStage;
#pragma unroll
    for (int mt = 0; mt < 2; mt++) {
        int rl = wid * 32 + mt * 16 + (lid >> 2);
#pragma unroll
        for (int nt = 0; nt < 2; nt++) {
            int c = nt * 8 + (lid & 3) * 2;
            *(float2*)(sM + rl * 34 + c)            = make_float2(accS[mt][nt][0], accS[mt][nt][1]);
            *(float2*)(sM + (rl + 8) * 34 + c)      = make_float2(accS[mt][nt][2], accS[mt][nt][3]);
            *(float2*)(sM + rl * 34 + 16 + c)       = make_float2(accR[mt][nt][0], accR[mt][nt][1]);
            *(float2*)(sM + (rl + 8) * 34 + 16 + c) = make_float2(accR[mt][nt][2], accR[mt][nt][3]);
        }
    }
    __syncthreads();

    const int r = tid;
    const float* mrow = sM + r * 34;
    u16* MH = g_Mhi + (size_t)b * NF * NR + r0 + r;
    u16* ML = g_Mlo + (size_t)b * NF * NR + r0 + r;
#pragma unroll 8
    for (int f = 0; f < 32; f++) {
        uint32_t h32, l32;
        split2(mrow[f], 0.f, h32, l32);
        MH[(size_t)f * NR] = (u16)h32;
        ML[(size_t)f * NR] = (u16)l32;
    }
    const float* Rab = Ra + (size_t)b * DR * NR + r0 + r;
#pragma unroll
    for (int j = 0; j < 8; j++) {
        uint32_t h32, l32;
        split2(Rab[(size_t)j * NR], 0.f, h32, l32);
        MH[(size_t)(32 + j) * NR] = (u16)h32;
        ML[(size_t)(32 + j) * NR] = (u16)l32;
    }
}

// ============================================================================
// Kernel B: G[z][b][o][f] = sum_{r in z} Rr[b,o,r] * Bm[b,f,r]  (f<40),
// f=40 -> s[o]. bf16 3-limb mma. 4-stage cp.async pipeline:
//  - Rr staged RAW fp32 (cp.async, zero regs); A-fragments built in compute
//    phase via direct ld.shared.v2.f32 at mma coordinates + in-reg split.
//  - Bm limbs cp.async'd straight into the ldsm tiles.
// CTA 128o x 48f, 8 warps (16o each), KC=32. grid (16,4,4)=256 CTAs, 2/SM.
// ============================================================================
__global__ void __launch_bounds__(256, 2)
kernelB(const float* __restrict__ Rr)
{
    extern __shared__ __align__(128) char sB[];

    const int tid = threadIdx.x;
    const int wid = tid >> 5;
    const int lid = tid & 31;
    const int o0  = blockIdx.x * 128;
    const int b   = blockIdx.y;
    const int z   = blockIdx.z;

    const uint32_t uB0 = smem_u32(sB);

    const float* Ag  = Rr    + (size_t)b * NO * NR + (size_t)z * KZ;
    const u16*   BgH = g_Mhi + (size_t)b * NF * NR + (size_t)z * KZ;
    const u16*   BgL = g_Mlo + (size_t)b * NF * NR + (size_t)z * KZ;

    // cp.async staging maps
    const int arow = tid >> 1;            // 0..127
    const int aq   = (tid & 1) * 16;      // float offset (64B half-row)
    const int brow = tid >> 2;            // 0..63 (only <40 used)
    const int bq   = (tid & 3) * 8;       // u16 offset (16B quarter)

    // A-fragment LDS coordinates (m16n8k16 row-major A)
    const uint32_t aR  = (uint32_t)(wid * 16 + (lid >> 2));     // fragment row
    const uint32_t aK8 = (uint32_t)((lid & 3) * 8);             // k byte offset
    // B-fragment ldsm map (unchanged, verified)
    const uint32_t b_lrow = (uint32_t)((((lid >> 3) >> 1) * 8) + (lid & 7));
    const uint32_t b_lcol = (uint32_t)(((lid >> 3) & 1) * 8);

    // init constant rows 40..47 of Bh/Bl in ALL stages (cp.async never writes them)
    for (int idx = tid; idx < NST * 320; idx += 256) {
        int stage = idx / 320, rem = idx - stage * 320;
        int limb = rem / 160, off4 = (rem - limb * 160) * 4;
        int byteoff = stage * STSZ + (limb ? SOF_BL : SOF_BH) + 40 * BPIT + off4;
        uint32_t val = (limb == 0 && off4 < BPIT) ? 0x3F803F80u : 0u;
        *(uint32_t*)(sB + byteoff) = val;
    }

    float acc[6][4];
#pragma unroll
    for (int j = 0; j < 6; j++)
#pragma unroll
        for (int v = 0; v < 4; v++) acc[j][v] = 0.f;

#define CPSTAGE(cb, base) do {                                                \
    {                                                                         \
        const float* ap = Ag + (size_t)(o0 + arow) * NR + (cb) + aq;          \
        uint32_t d = (base) + (uint32_t)arow * APIT + (uint32_t)aq * 4;       \
        cpasync16(d,      ap);                                                \
        cpasync16(d + 16, ap + 4);                                            \
        cpasync16(d + 32, ap + 8);                                            \
        cpasync16(d + 48, ap + 12);                                           \
    }                                                                         \
    if (brow < NF) {                                                          \
        const u16* sh = BgH + (size_t)brow * NR + (cb) + bq;                  \
        const u16* sl = BgL + (size_t)brow * NR + (cb) + bq;                  \
        uint32_t d = (base) + SOF_BH + (uint32_t)brow * BPIT + (uint32_t)bq * 2; \
        cpasync16(d, sh);                                                     \
        cpasync16(d + (SOF_BL - SOF_BH), sl);                                 \
    }                                                                         \
} while (0)

    // prologue: stages 0..2 in flight
    CPSTAGE(0, uB0);                 CP_COMMIT();
    CPSTAGE(KC, uB0 + STSZ);         CP_COMMIT();
    CPSTAGE(2 * KC, uB0 + 2 * STSZ); CP_COMMIT();

    for (int kc = 0; kc < NCH; kc++) {
        const uint32_t cbase = uB0 + (uint32_t)(kc & (NST - 1)) * STSZ;

        CP_WAIT2();          // stage kc complete (<=2 groups still in flight)
        __syncthreads();

        // refill: stage kc+3 into buffer (kc+3)%4 = (kc-1)%4 (safe post-sync)
        if (kc + 3 < NCH) {
            const uint32_t nb = uB0 + (uint32_t)((kc + 3) & (NST - 1)) * STSZ;
            CPSTAGE((kc + 3) * KC, nb);
        }
        CP_COMMIT();

        // compute chunk kc
#pragma unroll
        for (int ks = 0; ks < 2; ks++) {
            // A fragment: direct fp32 LDS + split (rows aR, aR+8; k, k+8)
            uint32_t abase = cbase + aR * APIT + aK8 + (uint32_t)(ks * 64);
            float2 v0 = lds64f(abase);
            float2 v1 = lds64f(abase + 8 * APIT);
            float2 v2 = lds64f(abase + 32);
            float2 v3 = lds64f(abase + 8 * APIT + 32);
            uint32_t ah[4], al[4];
            split2(v0.x, v0.y, ah[0], al[0]);
            split2(v1.x, v1.y, ah[1], al[1]);
            split2(v2.x, v2.y, ah[2], al[2]);
            split2(v3.x, v3.y, ah[3], al[3]);

            const uint32_t koff = (uint32_t)(ks * 16) * 2;
            uint32_t bh[6][2], bl[6][2];
#pragma unroll
            for (int tp = 0; tp < 3; tp++) {
                uint32_t addr = cbase + SOF_BH + (b_lrow + tp * 16) * BPIT + b_lcol * 2 + koff;
                uint32_t rh[4], rl[4];
                ldm_x4(rh, addr);
                ldm_x4(rl, addr + (SOF_BL - SOF_BH));
                bh[2 * tp][0] = rh[0]; bh[2 * tp][1] = rh[1];
                bh[2 * tp + 1][0] = rh[2]; bh[2 * tp + 1][1] = rh[3];
                bl[2 * tp][0] = rl[0]; bl[2 * tp][1] = rl[1];
                bl[2 * tp + 1][0] = rl[2]; bl[2 * tp + 1][1] = rl[3];
            }
#pragma unroll
            for (int nt = 0; nt < 5; nt++) {
                mma16816(acc[nt], ah, bh[nt]);
                mma16816(acc[nt], ah, bl[nt]);
                mma16816(acc[nt], al, bh[nt]);
            }
            mma16816(acc[5], ah, bh[5]);
            mma16816(acc[5], al, bh[5]);
        }
    }
#undef CPSTAGE

    // epilogue: D frag -> g_Ehp[z][b][o][48]
    float* outb = g_Ehp + ((size_t)(z * BATCH + b) * NO) * NFP;
    int o = o0 + wid * 16 + (lid >> 2);
#pragma unroll
    for (int nt = 0; nt < 6; nt++) {
        int f = nt * 8 + (lid & 3) * 2;
        *(float2*)(outb + (size_t)o * NFP + f)       = make_float2(acc[nt][0], acc[nt][1]);
        *(float2*)(outb + (size_t)(o + 8) * NFP + f) = make_float2(acc[nt][2], acc[nt][3]);
    }
}

// ============================================================================
// Kernel C: fold W_r into the object model:
//   P = W_ox@[O;X] + Wc@G + wb*s + b_o ; scores = W_s@P + b_s ; softmax.
// ============================================================================
__global__ void __launch_bounds__(128, 1)
kernelC(const float* __restrict__ O, const float* __restrict__ X,
        const float* __restrict__ Wr, const float* __restrict__ br,
        const float* __restrict__ Wo, const float* __restrict__ bo,
        const float* __restrict__ Ws, const float* __restrict__ bs,
        float* __restrict__ out)
{
    __shared__ u64 sWox[24 * 32];
    __shared__ u64 sWc[NF * 32];
    __shared__ u64 sWoE[64 * 32];
    __shared__ float sWr[64 * NF];
    __shared__ u64 sWs[NC * 32];
    __shared__ u64 swb[32];
    __shared__ float sbo[DP];
    __shared__ float sbs[NC];
    __shared__ float sbr_[DE];

    const int tid = threadIdx.x;
    const int b   = blockIdx.y;
    const int o   = blockIdx.x * 128 + tid;

    for (int idx = tid; idx < 24 * 32; idx += 128) {
        int f = idx >> 5, p2 = idx & 31;
        sWox[idx] = pack2(Wo[(size_t)(2 * p2) * 88 + f],
                          Wo[(size_t)(2 * p2 + 1) * 88 + f]);
    }
    for (int idx = tid; idx < 64 * 32; idx += 128) {
        int e = idx >> 5, p2 = idx & 31;
        sWoE[idx] = pack2(Wo[(size_t)(2 * p2) * 88 + 24 + e],
                          Wo[(size_t)(2 * p2 + 1) * 88 + 24 + e]);
    }
    for (int idx = tid; idx < 64 * NF; idx += 128) sWr[idx] = Wr[idx];
    for (int idx = tid; idx < NC * 32; idx += 128) {
        int c = idx >> 5, p2 = idx & 31;
        float2 w = *(const float2*)(Ws + (size_t)c * DP + 2 * p2);
        sWs[idx] = pack2(w.x, w.y);
    }
    if (tid < DP) sbo[tid] = bo[tid];
    if (tid < NC) sbs[tid] = bs[tid];
    if (tid < DE) sbr_[tid] = br[tid];
    __syncthreads();

    for (int idx = tid; idx < NF * 32; idx += 128) {
        int f = idx >> 5, p2 = idx & 31;
        u64 a = 0ull;
#pragma unroll 8
        for (int e = 0; e < 64; e++) {
            float w = sWr[e * NF + f];
            a = ffma2(sWoE[e * 32 + p2], pack2(w, w), a);
        }
        sWc[idx] = a;
    }
    if (tid < 32) {
        u64 a = 0ull;
#pragma unroll 8
        for (int e = 0; e < 64; e++)
            a = ffma2(sWoE[e * 32 + tid], pack2(sbr_[e], sbr_[e]), a);
        swb[tid] = a;
    }
    __syncthreads();

    u64 P[32];
#pragma unroll
    for (int p2 = 0; p2 < 32; p2++) P[p2] = pack2(sbo[2 * p2], sbo[2 * p2 + 1]);

    const float* Ob = O + (size_t)b * DS * NO + o;
    const float* Xb = X + (size_t)b * DX * NO + o;

#pragma unroll 4
    for (int f = 0; f < DS; f++) {
        float cf = Ob[(size_t)f * NO];
        u64 c2 = pack2(cf, cf);
        const u64* wrow = sWox + f * 32;
#pragma unroll
        for (int p2 = 0; p2 < 32; p2++) P[p2] = ffma2(wrow[p2], c2, P[p2]);
    }
#pragma unroll 4
    for (int f = 0; f < DX; f++) {
        float cf = Xb[(size_t)f * NO];
        u64 c2 = pack2(cf, cf);
        const u64* wrow = sWox + (DS + f) * 32;
#pragma unroll
        for (int p2 = 0; p2 < 32; p2++) P[p2] = ffma2(wrow[p2], c2, P[p2]);
    }

    const float* ep0 = g_Ehp + ((size_t)b * NO + o) * NFP;
    const size_t SSTR = (size_t)BATCH * NO * NFP;
#pragma unroll 2
    for (int f4 = 0; f4 < 10; f4++) {
        float4 v0 = *(const float4*)(ep0 + 4 * f4);
        float4 v1 = *(const float4*)(ep0 + SSTR + 4 * f4);
        float4 v2 = *(const float4*)(ep0 + 2 * SSTR + 4 * f4);
        float4 v3 = *(const float4*)(ep0 + 3 * SSTR + 4 * f4);
        float cf[4] = {(v0.x + v1.x) + (v2.x + v3.x),
                       (v0.y + v1.y) + (v2.y + v3.y),
                       (v0.z + v1.z) + (v2.z + v3.z),
                       (v0.w + v1.w) + (v2.w + v3.w)};
#pragma unroll
        for (int j = 0; j < 4; j++) {
            u64 c2 = pack2(cf[j], cf[j]);
            const u64* wrow = sWc + (4 * f4 + j) * 32;
#pragma unroll
            for (int p2 = 0; p2 < 32; p2++) P[p2] = ffma2(wrow[p2], c2, P[p2]);
        }
    }
    {
        float s = (ep0[40] + ep0[40 + SSTR]) + (ep0[40 + 2 * SSTR] + ep0[40 + 3 * SSTR]);
        u64 c2 = pack2(s, s);
#pragma unroll
        for (int p2 = 0; p2 < 32; p2++) P[p2] = ffma2(swb[p2], c2, P[p2]);
    }

    float sc[NC];
#pragma unroll
    for (int c = 0; c < NC; c++) {
        const u64* wrow = sWs + c * 32;
        u64 acc = 0ull;
#pragma unroll
        for (int p2 = 0; p2 < 32; p2++) acc = ffma2(wrow[p2], P[p2], acc);
        float2 a = unpack2(acc);
        sc[c] = a.x + a.y + sbs[c];
    }

    float mx = sc[0];
#pragma unroll
    for (int c = 1; c < NC; c++) mx = fmaxf(mx, sc[c]);
    float sum = 0.f;
#pragma unroll
    for (int c = 0; c < NC; c++) { sc[c] = expf(sc[c] - mx); sum += sc[c]; }
    float inv = 1.f / sum;
#pragma unroll
    for (int c = 0; c < NC; c++)
        out[((size_t)b * NC + c) * NO + o] = sc[c] * inv;
}

// ============================================================================
extern "C" void kernel_launch(void* const* d_in, const int* in_sizes, int n_in,
                              void* d_out, int out_size)
{
    const float* O  = (const float*)d_in[0];
    const float* Rs = (const float*)d_in[1];
    const float* Rr = (const float*)d_in[2];
    const float* Ra = (const float*)d_in[3];
    const float* X  = (const float*)d_in[4];
    const float* Wr = (const float*)d_in[5];
    const float* br = (const float*)d_in[6];
    const float* Wo = (const float*)d_in[7];
    const float* bo = (const float*)d_in[8];
    const float* Ws = (const float*)d_in[9];
    const float* bs = (const float*)d_in[10];
    float* out = (float*)d_out;
    (void)in_sizes; (void)n_in; (void)out_size;

    int smB = NST * STSZ;   // 112640 B
    cudaFuncSetAttribute(kernelB, cudaFuncAttributeMaxDynamicSharedMemorySize, smB);

    kernelA<<<dim3(NR / RT, BATCH), 256>>>(O, Rs, Rr, Ra);
    kernelB<<<dim3(NO / 128, BATCH, ZB), 256, smB>>>(Rr);
    kernelC<<<dim3(NO / 128, BATCH), 128>>>(O, X, Wr, br, Wo, bo, Ws, bs, out);
}